// round 12
// baseline (speedup 1.0000x reference)
#include <cuda_runtime.h>
#include <cuda_fp16.h>
#include <mma.h>
#include <cstdint>

using namespace nvcuda;

// Problem constants
#define Bb 8
#define Cc 64
#define Nn 500
#define Tt 12
#define Hh 4
#define Ff 64
#define Ss (Bb * Tt)   // 96 slices (b,t)
#define HF (Hh * Ff)   // 256
#define MAXD 128
#define ROWPAD 16
#define ALPHAc 0.05f
#define LEAKc 0.2f

// ---------------- scratch (device globals; no allocation) ----------------
__device__ float   g_xT[Ss * Nn * Cc];                   // [s,n,c] fp32 (final path)
__device__ __half  g_xT16[Ss * Nn * Cc];                 // fp16 iterates
__device__ __half  g_h1T16[Ss * Nn * Cc];
__device__ __half  g_h2T16[Ss * Nn * Cc];
__device__ __half  g_Wh16[(size_t)Ss * Nn * HF];         // [s,n,hf] fp16
__device__ __half  g_hpr16[((size_t)Ss * Nn + ROWPAD) * HF]; // padded for OOB frag rows
__device__ float   g_e1v[Ss * Nn * 4];                   // [(s*N+n)*4 + h]
__device__ float   g_e2v[Ss * Nn * 4];
__device__ __half  g_Wcat16[Cc * HF];                    // [c, h*F+f] fp16
__device__ __half  g_WgT16[HF * Cc];                     // [hf, o] fp16
__device__ float   g_WmT[3 * Cc * Cc];                   // [c_global, o]
__device__ int     g_cnt[Nn];
__device__ int     g_nbr[Nn * MAXD];

// ================= merged prep: nbr list + weight layouts + input transpose =========
__global__ void prep_all(const float* __restrict__ adj,
                         const float* __restrict__ W,
                         const float* __restrict__ Wg,
                         const float* __restrict__ Wm,
                         const float* __restrict__ x,
                         float* __restrict__ xT) {
    __shared__ float sm[16][193];
    const int blk = blockIdx.x;
    if (blk < 125) {
        if (threadIdx.x >= 128) return;
        int warp = threadIdx.x >> 5;
        int lane = threadIdx.x & 31;
        int n = blk * 4 + warp;
        if (n >= Nn) return;
        int base = 0;
        for (int m0 = 0; m0 < 512; m0 += 32) {
            int m = m0 + lane;
            bool p = (m < Nn) && (adj[n * Nn + m] > 0.f || m == n);
            unsigned mask = __ballot_sync(0xffffffffu, p);
            if (p) {
                int r = __popc(mask & ((1u << lane) - 1));
                if (base + r < MAXD) g_nbr[n * MAXD + base + r] = m;
            }
            base += __popc(mask);
        }
        if (lane == 0) g_cnt[n] = base < MAXD ? base : MAXD;
    } else if (blk < 189) {
        int i = (blk - 125) * 256 + threadIdx.x;
        if (i < Hh * Cc * Ff) {  // Wcat16[c, h*F+f] = W[h,c,f]
            int f = i % Ff; int rest = i / Ff;
            int c = rest % Cc; int h = rest / Cc;
            g_Wcat16[c * HF + h * Ff + f] = __float2half_rn(W[(h * Cc + c) * Ff + f]);
        }
        if (i < HF * Cc) {       // WgT16[hf, o] = half(Wg[o, hf])
            int o = i % Cc; int hf = i / Cc;
            g_WgT16[hf * Cc + o] = __float2half_rn(Wg[o * HF + hf]);
        }
        if (i < 3 * Cc * Cc) {   // WmT[c, o] = Wm[o, c]
            int o = i % Cc; int c = i / Cc;
            g_WmT[c * Cc + o] = Wm[o * (3 * Cc) + c];
        }
    } else {
        // transpose: x[b,c,n,t] -> xT[s,n,c] (fp32 + fp16)
        if (threadIdx.x >= 192) return;
        const int bi = blk - 189;
        const int nb = bi & 31, cb = (bi >> 5) & 3, b = bi >> 7;
        const int c0 = cb * 16, n0 = nb * 16;
        const int tt_ = threadIdx.x;
        const int ni_l = tt_ / 12, tl = tt_ % 12;
        const int n_l = n0 + ni_l;
        #pragma unroll
        for (int ci = 0; ci < 16; ++ci) {
            float v = 0.f;
            if (n_l < Nn)
                v = x[(((size_t)b * Cc + c0 + ci) * Nn + n_l) * Tt + tl];
            sm[ci][tt_] = v;
        }
        __syncthreads();
        #pragma unroll
        for (int rep = 0; rep < 16; ++rep) {
            int idx = rep * 192 + tt_;
            int ci = idx & 15;
            int rest = idx >> 4;
            int ni = rest / 12, t = rest % 12;
            int n = n0 + ni;
            if (n < Nn) {
                size_t oi = (((size_t)(b * Tt + t) * Nn) + n) * Cc + c0 + ci;
                float v = sm[ci][rest];
                xT[oi] = v;
                g_xT16[oi] = __float2half_rn(v);
            }
        }
    }
}

// ================= fp16 HMMA projection GEMM (2 heads/block) + e-vec + fp16 Wh ======
// grid (Ss, 8, 2), block 256 (8 warps). Tile 64 rows x 128 cols (heads 2z, 2z+1), K=64.
#define PAS_LD 72
#define PBS_LD 136
#define PCS_LD 132
__global__ void gemm_proj16(const __half* __restrict__ Ain,
                            const float* __restrict__ a1,
                            const float* __restrict__ a2) {
    __shared__ __align__(16) char smemRaw[64 * PCS_LD * 4];      // 33792 B
    __half (*As)[PAS_LD] = (__half(*)[PAS_LD])smemRaw;           // 9216 B
    __half (*Bs)[PBS_LD] = (__half(*)[PBS_LD])(smemRaw + 64 * PAS_LD * 2); // 17408 B
    float (*Cs)[PCS_LD] = (float(*)[PCS_LD])smemRaw;             // reuse after MMA

    const int s = blockIdx.x;
    const int r0 = blockIdx.y * 64;
    const int z = blockIdx.z;            // head pair
    const int c0 = z * 128;
    const int tid = threadIdx.x;
    const int wid = tid >> 5;
    const int wm = wid & 3, wn = wid >> 2;   // rows wm*16, cols wn*64
    const size_t rowB = (size_t)s * Nn;

    // stage A: 64 rows x 64 halfs (8 uint4/row), 2 uint4/thread
    {
        const uint4* srcA = (const uint4*)(Ain + rowB * Cc);
        #pragma unroll
        for (int k = 0; k < 2; ++k) {
            int idx = k * 256 + tid;
            int r = idx >> 3, p = idx & 7;
            int row = r0 + r;
            uint4 v = make_uint4(0, 0, 0, 0);
            if (row < Nn) v = srcA[(size_t)row * 8 + p];
            *(uint4*)&As[r][p * 8] = v;
        }
    }
    // stage B: Wcat16 rows 0..63, cols c0..c0+127 (16 uint4/row), 4 uint4/thread
    {
        const uint4* srcB = (const uint4*)(g_Wcat16 + c0);
        #pragma unroll
        for (int k = 0; k < 4; ++k) {
            int idx = k * 256 + tid;
            int r = idx >> 4, p = idx & 15;
            *(uint4*)&Bs[r][p * 8] = srcB[r * 32 + p];   // row stride 256 half = 32 uint4
        }
    }
    __syncthreads();

    wmma::fragment<wmma::accumulator, 16, 16, 16, float> fc[4];
    #pragma unroll
    for (int j = 0; j < 4; ++j) wmma::fill_fragment(fc[j], 0.f);
    #pragma unroll
    for (int k0 = 0; k0 < 64; k0 += 16) {
        wmma::fragment<wmma::matrix_a, 16, 16, 16, __half, wmma::row_major> fa;
        wmma::load_matrix_sync(fa, &As[wm * 16][k0], PAS_LD);
        #pragma unroll
        for (int j = 0; j < 4; ++j) {
            wmma::fragment<wmma::matrix_b, 16, 16, 16, __half, wmma::row_major> fb;
            wmma::load_matrix_sync(fb, &Bs[k0][wn * 64 + j * 16], PBS_LD);
            wmma::mma_sync(fc[j], fa, fb, fc[j]);
        }
    }
    __syncthreads();   // done reading As/Bs; reuse as Cs
    #pragma unroll
    for (int j = 0; j < 4; ++j)
        wmma::store_matrix_sync(&Cs[wm * 16][wn * 64 + j * 16], fc[j], PCS_LD,
                                wmma::mem_row_major);
    __syncthreads();

    // fused e-vec for both heads (interleaved [n][4] layout) -- fp32, exact logits
    {
        const int row = tid >> 2, q = tid & 3;
        #pragma unroll
        for (int hh = 0; hh < 2; ++hh) {
            const int hg = z * 2 + hh;           // global head
            float s1 = 0.f, s2 = 0.f;
            #pragma unroll
            for (int i = 0; i < 16; ++i) {
                int cl = hh * 64 + q * 16 + i;
                float v = Cs[row][cl];
                s1 = fmaf(v, a1[hg * Ff + q * 16 + i], s1);
                s2 = fmaf(v, a2[hg * Ff + q * 16 + i], s2);
            }
            s1 += __shfl_xor_sync(0xffffffffu, s1, 1);
            s2 += __shfl_xor_sync(0xffffffffu, s2, 1);
            s1 += __shfl_xor_sync(0xffffffffu, s1, 2);
            s2 += __shfl_xor_sync(0xffffffffu, s2, 2);
            if (q == 0 && r0 + row < Nn) {
                g_e1v[(rowB + r0 + row) * 4 + hg] = s1;
                g_e2v[(rowB + r0 + row) * 4 + hg] = s2;
            }
        }
    }

    // fp16 Wh store (coalesced): 64 rows x 64 half2
    __half2* dst = (__half2*)g_Wh16;
    #pragma unroll
    for (int k = 0; k < 16; ++k) {
        int idx = k * 256 + tid;
        int r = idx >> 6, p = idx & 63;
        if (r0 + r < Nn) {
            dst[(rowB + r0 + r) * (HF / 2) + z * 64 + p] =
                __floats2half2_rn(Cs[r][2 * p], Cs[r][2 * p + 1]);
        }
    }
}

// ================= attention: SMEM-cached Wh tile, block per (head, slice) ==========
// grid (Hh, Ss), 512 threads, 68KB dyn smem.
// Stage Wh[500][64] fp16 head slice + e1/e2 vectors; warp-per-node softmax + LDS gather.
#define ATTN_THREADS 512
#define SWH_BYTES (Nn * Ff * 2)              // 64000
#define ATTN_SMEM (SWH_BYTES + Nn * 4 * 2)   // + e1,e2 = 68000

__global__ __launch_bounds__(ATTN_THREADS)
void attn_agg() {
    extern __shared__ __align__(16) char asmem[];
    __half (*sWh)[Ff] = (__half(*)[Ff])asmem;
    float* sE1 = (float*)(asmem + SWH_BYTES);
    float* sE2 = (float*)(asmem + SWH_BYTES + Nn * 4);

    const int h = blockIdx.x, s = blockIdx.y;
    const int tid = threadIdx.x;
    const size_t rowB = (size_t)s * Nn;

    // stage: head slice of Wh (500 rows x 8 uint4) + e vectors
    {
        const uint4* src = (const uint4*)g_Wh16;     // row = 32 uint4
        for (int i = tid; i < Nn * 8; i += ATTN_THREADS) {
            int r = i >> 3, p = i & 7;
            *(uint4*)&sWh[r][p * 8] = src[(rowB + r) * 32 + h * 8 + p];
        }
        for (int i = tid; i < Nn; i += ATTN_THREADS) {
            sE1[i] = g_e1v[(rowB + i) * 4 + h];
            sE2[i] = g_e2v[(rowB + i) * 4 + h];
        }
    }
    __syncthreads();

    const int wid = tid >> 5, lane = tid & 31;
    const __half2 hz = __float2half2_rn(0.f);

    for (int n = wid; n < Nn; n += ATTN_THREADS / 32) {
        const int cnt = min(g_cnt[n], MAXD);
        const float e1v = sE1[n];
        int mv[4];
        float ev[4];
        unsigned wv[4];
        float mx = -1e30f;
        #pragma unroll
        for (int k = 0; k < 4; ++k) {
            int j = k * 32 + lane;
            float e = -1e30f; int m = 0;
            if (k * 32 < cnt && j < cnt) {
                m = g_nbr[n * MAXD + j];
                float tv = e1v + sE2[m];
                e = tv > 0.f ? tv : LEAKc * tv;
            }
            mv[k] = m; ev[k] = e;
            mx = fmaxf(mx, e);
        }
        #pragma unroll
        for (int o = 16; o; o >>= 1) mx = fmaxf(mx, __shfl_xor_sync(0xffffffffu, mx, o));
        float sum = 0.f;
        #pragma unroll
        for (int k = 0; k < 4; ++k) {
            float w = (k * 32 + lane < cnt) ? __expf(ev[k] - mx) : 0.f;
            ev[k] = w;
            sum += w;
        }
        #pragma unroll
        for (int o = 16; o; o >>= 1) sum += __shfl_xor_sync(0xffffffffu, sum, o);
        const float inv = 1.f / sum;
        #pragma unroll
        for (int k = 0; k < 4; ++k) {
            __half2 hw = __float2half2_rn(ev[k] * inv);
            wv[k] = *(unsigned*)&hw;
        }

        // gather from smem: lane owns feature pair `lane` (2 halfs)
        __half2 accA = hz, accB = hz;
        #pragma unroll
        for (int k = 0; k < 4; ++k) {
            if (k * 32 >= cnt) break;
            const int lim = min(32, cnt - k * 32);
            #pragma unroll 8
            for (int sl = 0; sl < lim; ++sl) {
                int m = __shfl_sync(0xffffffffu, mv[k], sl);
                unsigned wu = __shfl_sync(0xffffffffu, wv[k], sl);
                __half2 d = *(__half2*)&sWh[m][2 * lane];
                if (sl & 1) accB = __hfma2(d, *(__half2*)&wu, accB);
                else        accA = __hfma2(d, *(__half2*)&wu, accA);
            }
        }
        float2 fa = __half22float2(accA);
        float2 fb = __half22float2(accB);
        float vx = fa.x + fb.x, vy = fa.y + fb.y;
        vx = vx > 0.f ? vx : (__expf(vx) - 1.f);
        vy = vy > 0.f ? vy : (__expf(vy) - 1.f);
        ((__half2*)g_hpr16)[(rowB + n) * (HF / 2) + h * 32 + lane] =
            __floats2half2_rn(vx, vy);
    }
}

// ================= fp16 wmma mix GEMM: h_next16 = a*x16 + (1-a)*(hpr16 @ WgT16 + bg) ==
// grid (Ss, 8), block 256 (8 warps). A fragments loaded straight from global.
#define MBS_LD 72
__global__ void gemm_mix_tc(const float* __restrict__ bias,
                            const __half* __restrict__ resid16,
                            __half* __restrict__ Cm16) {
    __shared__ __align__(16) char smemRaw[256 * MBS_LD * 2];   // Bs, reused as Cs
    __half (*Bs)[MBS_LD] = (__half(*)[MBS_LD])smemRaw;
    float (*Cs)[68] = (float(*)[68])smemRaw;                   // 17408 <= 36864

    const int s = blockIdx.x;
    const int r0 = blockIdx.y * 64;
    const int tid = threadIdx.x;
    const int wid = tid >> 5;
    const int wm = wid & 3, wn = wid >> 2;

    // stage B: 256 rows x 64 halfs (8 uint4/row), 8 uint4/thread
    {
        const uint4* src = (const uint4*)g_WgT16;
        #pragma unroll
        for (int k = 0; k < 8; ++k) {
            int idx = k * 256 + tid;
            int r = idx >> 3, p = idx & 7;
            *(uint4*)&Bs[r][p * 8] = src[r * 8 + p];
        }
    }
    __syncthreads();

    const __half* Aslice = g_hpr16 + (size_t)s * Nn * HF;      // padded tail -> safe OOB rows
    wmma::fragment<wmma::accumulator, 16, 16, 16, float> fc[2];
    wmma::fill_fragment(fc[0], 0.f);
    wmma::fill_fragment(fc[1], 0.f);
    #pragma unroll
    for (int k0 = 0; k0 < HF; k0 += 16) {
        wmma::fragment<wmma::matrix_a, 16, 16, 16, __half, wmma::row_major> fa;
        wmma::load_matrix_sync(fa, Aslice + (size_t)(r0 + wm * 16) * HF + k0, HF);
        #pragma unroll
        for (int sub = 0; sub < 2; ++sub) {
            wmma::fragment<wmma::matrix_b, 16, 16, 16, __half, wmma::row_major> fb;
            wmma::load_matrix_sync(fb, &Bs[k0][wn * 32 + sub * 16], MBS_LD);
            wmma::mma_sync(fc[sub], fa, fb, fc[sub]);
        }
    }
    __syncthreads();   // all warps done reading Bs; reuse as Cs
    wmma::store_matrix_sync(&Cs[wm * 16][wn * 32], fc[0], 68, wmma::mem_row_major);
    wmma::store_matrix_sync(&Cs[wm * 16][wn * 32 + 16], fc[1], 68, wmma::mem_row_major);
    __syncthreads();

    #pragma unroll
    for (int k = 0; k < 16; ++k) {
        int idx = k * 256 + tid;
        int r = idx >> 6, c = idx & 63;
        int row = r0 + r;
        if (row < Nn) {
            size_t oidx = ((size_t)s * Nn + row) * Cc + c;
            float v = ALPHAc * __half2float(resid16[oidx])
                    + (1.f - ALPHAc) * (Cs[r][c] + bias[c]);
            Cm16[oidx] = __float2half_rn(v);
        }
    }
}

// ---------------- final: out[b,o,n,t] = bm[o] + Wm @ [x; h1; h2] ----------------
__global__ void final_out(const float* __restrict__ xT,
                          const __half* __restrict__ h1,
                          const __half* __restrict__ h2,
                          const float* __restrict__ bm,
                          float* __restrict__ out) {
    __shared__ float sX[16][64], sH1[16][64], sH2[16][64];
    const int s = blockIdx.x;
    const int n0 = blockIdx.y * 16;
    const int tid = threadIdx.x;
    for (int i = tid; i < 16 * 64; i += 256) {
        int nl = i >> 6, c = i & 63;
        int n = n0 + nl;
        size_t idx = ((size_t)s * Nn + (n < Nn ? n : 0)) * Cc + c;
        sX[nl][c]  = (n < Nn) ? xT[idx] : 0.f;
        sH1[nl][c] = (n < Nn) ? __half2float(h1[idx]) : 0.f;
        sH2[nl][c] = (n < Nn) ? __half2float(h2[idx]) : 0.f;
    }
    __syncthreads();
    const int o = tid & 63, ng = tid >> 6;
    float acc[4] = {0.f, 0.f, 0.f, 0.f};
    #pragma unroll 4
    for (int c = 0; c < 64; ++c) {
        float w0 = g_WmT[c * Cc + o];
        float w1 = g_WmT[(64 + c) * Cc + o];
        float w2 = g_WmT[(128 + c) * Cc + o];
        #pragma unroll
        for (int r = 0; r < 4; ++r) {
            int nl = ng + r * 4;
            acc[r] = fmaf(w0, sX[nl][c], fmaf(w1, sH1[nl][c], fmaf(w2, sH2[nl][c], acc[r])));
        }
    }
    const int b = s / Tt, t = s % Tt;
    const float bias = bm[o];
    #pragma unroll
    for (int r = 0; r < 4; ++r) {
        int n = n0 + ng + r * 4;
        if (n < Nn)
            out[(((size_t)b * Cc + o) * Nn + n) * Tt + t] = acc[r] + bias;
    }
}

// ---------------- launch ----------------
extern "C" void kernel_launch(void* const* d_in, const int* in_sizes, int n_in,
                              void* d_out, int out_size) {
    const float* x   = (const float*)d_in[0];
    const float* adj = (const float*)d_in[1];
    const float* W   = (const float*)d_in[2];
    const float* a1  = (const float*)d_in[3];
    const float* a2  = (const float*)d_in[4];
    const float* Wg  = (const float*)d_in[5];
    const float* bg  = (const float*)d_in[6];
    const float* Wm  = (const float*)d_in[7];
    const float* bm  = (const float*)d_in[8];
    float* out = (float*)d_out;

    float* xT;
    __half *xT16, *h1T16, *h2T16;
    cudaGetSymbolAddress((void**)&xT,    g_xT);
    cudaGetSymbolAddress((void**)&xT16,  g_xT16);
    cudaGetSymbolAddress((void**)&h1T16, g_h1T16);
    cudaGetSymbolAddress((void**)&h2T16, g_h2T16);

    static bool attr_set = false;
    if (!attr_set) {
        cudaFuncSetAttribute(attn_agg,
                             cudaFuncAttributeMaxDynamicSharedMemorySize, ATTN_SMEM);
        attr_set = true;
    }

    prep_all<<<1213, 256>>>(adj, W, Wg, Wm, x, xT);

    const __half* hin16 = xT16;
    __half* hb16[2] = {h1T16, h2T16};
    for (int it = 0; it < 2; ++it) {
        gemm_proj16<<<dim3(Ss, 8, 2), 256>>>(hin16, a1, a2);
        attn_agg<<<dim3(Hh, Ss), ATTN_THREADS, ATTN_SMEM>>>();
        gemm_mix_tc<<<dim3(Ss, 8), 256>>>(bg, xT16, hb16[it]);
        hin16 = hb16[it];
    }
    final_out<<<dim3(Ss, (Nn + 15) / 16), 256>>>(xT, h1T16, h2T16, bm, out);
}